// round 15
// baseline (speedup 1.0000x reference)
#include <cuda_runtime.h>
#include <cuda_fp16.h>
#include <math.h>
#include <stdint.h>

// ---------------------------------------------------------------------------
// ENAS controller sampler. H=2048, NB=8, NC=8, TEMP=5, TANH_C=2.5, OP_RED=2.5
// R14: persistent megakernel (148 blocks x 1024 thr, 1/SM). w_hh fp16 slice
// (13 cols = 208KB) in SMEM + 8KB fp32 h stage -> ALL dots are fp16-weight x
// fp32-h in R8's exact accumulation order (R8 passed at 1.7e-5). Leftover 124
// cols served from a compact fp16 global copy via L2. Software grid barriers.
// ---------------------------------------------------------------------------

#define H 2048
#define G4 8192   // 4*H
#define NBLK 148
#define TPB 1024
#define CPB 13
#define XCOLS 124                    // 2048 - 148*13
#define SMEM_BYTES (CPB * 4 * H * 2) // 212992

// scratch layout (floats)
#define OFF_H0   0
#define OFF_H1   (OFF_H0 + H)
#define OFF_C    (OFF_H1 + H)
#define OFF_HW2  (OFF_C + H)
#define OFF_AW1  (OFF_HW2 + H)            // 10 x 2048
#define OFF_AXP  (OFF_AW1 + 10*H)         // 10 x 8192
#define OFF_EXP  (OFF_AXP + 10*G4)        // 9 x 8192
#define OFF_BSUM (OFF_EXP + 9*G4)         // 8192
#define SCR_TOTAL (OFF_BSUM + G4)

__device__ __align__(16) float    g_scratch[SCR_TOTAL];
__device__ int       g_sel[64];
__device__ unsigned  g_key[2];
__device__ float     g_acc[2];
__device__ unsigned           g_bar_ctr;
__device__ volatile unsigned  g_bar_gen;

// fp16 weights
__device__ __align__(16) __half g_wih_h[4 * H * H];
__device__ __align__(16) __half g_wa1_h[H * H];
__device__ __align__(16) __half g_wa2_h[H * H];
__device__ __align__(16) __half g_wsoft_h[8 * H];
// compact copy of w_hh gate-rows for leftover cols: row (g*XCOLS + e) is
// original w_hh row g*H + 1924 + e
__device__ __align__(16) __half g_whh_x[4 * XCOLS * H];

// ------------------------- grid barrier ------------------------------------
__device__ __forceinline__ void gbar()
{
    __syncthreads();
    if (threadIdx.x == 0) {
        __threadfence();
        unsigned gen = g_bar_gen;
        __threadfence();
        if (atomicAdd(&g_bar_ctr, 1u) == NBLK - 1) {
            g_bar_ctr = 0;
            __threadfence();
            g_bar_gen = gen + 1;
        } else {
            while (g_bar_gen == gen) __nanosleep(32);
        }
        __threadfence();
    }
    __syncthreads();
}

// ------------------------- Threefry-2x32 (20 rounds) -----------------------
__device__ __forceinline__ void tf2x32(unsigned k0, unsigned k1,
                                       unsigned x0, unsigned x1,
                                       unsigned &y0, unsigned &y1)
{
    const unsigned ks0 = k0, ks1 = k1, ks2 = k0 ^ k1 ^ 0x1BD11BDAu;
    x0 += ks0; x1 += ks1;
    const unsigned R[8] = {13u,15u,26u,6u,17u,29u,16u,24u};
    unsigned ks[3] = {ks0, ks1, ks2};
    #pragma unroll
    for (int i = 0; i < 5; i++) {
        #pragma unroll
        for (int j = 0; j < 4; j++) {
            unsigned r = R[(i & 1) * 4 + j];
            x0 += x1;
            x1 = (x1 << r) | (x1 >> (32u - r));
            x1 ^= x0;
        }
        x0 += ks[(i + 1) % 3];
        x1 += ks[(i + 2) % 3] + (unsigned)(i + 1);
    }
    y0 = x0; y1 = x1;
}

__device__ void do_sample(const float* l, int n, int* sel_slot, float* arc_out)
{
    unsigned k0 = g_key[0], k1 = g_key[1];
    unsigned nk0, nk1, s0, s1;
    tf2x32(k0, k1, 0u, 0u, nk0, nk1);
    tf2x32(k0, k1, 0u, 1u, s0, s1);
    g_key[0] = nk0; g_key[1] = nk1;

    int best = 0; float bz = -3.4e38f;
    for (int a = 0; a < n; a++) {
        unsigned b1, b2;
        tf2x32(s0, s1, 0u, (unsigned)a, b1, b2);
        unsigned bits = b1 ^ b2;
        float f = __uint_as_float((bits >> 9) | 0x3F800000u) - 1.0f;
        float u = (f == 0.0f) ? 1.17549435e-38f : f;
        float g = -logf(-logf(u));
        float z = l[a] + g;
        if (z > bz) { bz = z; best = a; }
    }
    float mx = l[0];
    for (int a = 1; a < n; a++) mx = fmaxf(mx, l[a]);
    float se = 0.0f;
    for (int a = 0; a < n; a++) se += expf(l[a] - mx);
    float lse = logf(se);
    g_acc[0] += -((l[best] - mx) - lse);
    float ent = 0.0f;
    for (int a = 0; a < n; a++) {
        float ls = (l[a] - mx) - lse;
        ent -= ls * expf(ls);
    }
    g_acc[1] += ent;
    *sel_slot = best;
    *arc_out = (float)best;
}

// ------------------------------ small kernels ------------------------------
__global__ void init_kernel(const float* __restrict__ b_ih,
                            const float* __restrict__ b_hh)
{
    int i = blockIdx.x * blockDim.x + threadIdx.x;  // 16384 threads
    float* scr = g_scratch;
    if (i < H) {
        scr[OFF_H0 + i] = 0.0f; scr[OFF_H1 + i] = 0.0f; scr[OFF_C + i] = 0.0f;
    }
    if (i < 2 * G4) scr[OFF_AXP + i] = 0.0f;
    if (i < G4)     scr[OFF_BSUM + i] = b_ih[i] + b_hh[i];
    if (i == 0) {
        g_key[0] = 0u; g_key[1] = 42u;
        g_acc[0] = 0.0f; g_acc[1] = 0.0f;
        g_bar_ctr = 0u;
    }
}

__device__ __forceinline__ void conv_seg(const float* __restrict__ s,
                                         __half* __restrict__ d,
                                         size_t n4, size_t tid, size_t stride)
{
    const float4* s4 = (const float4*)s;
    uint2* d4 = (uint2*)d;
    for (size_t i = tid; i < n4; i += stride) {
        float4 v = s4[i];
        __half2 a = __floats2half2_rn(v.x, v.y);
        __half2 b = __floats2half2_rn(v.z, v.w);
        d4[i] = make_uint2(*(unsigned*)&a, *(unsigned*)&b);
    }
}

__global__ void convert_kernel(const float* __restrict__ whh,
                               const float* __restrict__ wih,
                               const float* __restrict__ wa1,
                               const float* __restrict__ wa2,
                               const float* __restrict__ wsoft)
{
    size_t tid = (size_t)blockIdx.x * blockDim.x + threadIdx.x;
    size_t stride = (size_t)gridDim.x * blockDim.x;
    conv_seg(wih,   g_wih_h,   (size_t)4 * H * H / 4, tid, stride);
    conv_seg(wa1,   g_wa1_h,   (size_t)H * H / 4,     tid, stride);
    conv_seg(wa2,   g_wa2_h,   (size_t)H * H / 4,     tid, stride);
    conv_seg(wsoft, g_wsoft_h, (size_t)8 * H / 4,     tid, stride);
    // leftover w_hh cols -> compact fp16
    {
        const float4* s4 = (const float4*)whh;
        uint2* d4 = (uint2*)g_whh_x;
        size_t n4 = (size_t)4 * XCOLS * H / 4;
        for (size_t i = tid; i < n4; i += stride) {
            size_t r = i >> 9, c4 = i & 511;     // 512 float4 per row
            size_t g = r / XCOLS, e = r % XCOLS;
            size_t src = ((g * H) + 1924 + e) * 512 + c4;
            float4 v = s4[src];
            __half2 a = __floats2half2_rn(v.x, v.y);
            __half2 b = __floats2half2_rn(v.z, v.w);
            d4[i] = make_uint2(*(unsigned*)&a, *(unsigned*)&b);
        }
    }
}

// encoder_xproj[e][j] = sum_k enc[e,k] * w_ih[j,k]; warp-per-row
__global__ void __launch_bounds__(256)
encproj_kernel(const float* __restrict__ enc)
{
    int t = threadIdx.x;
    int w = t >> 5, lane = t & 31;
    int j = blockIdx.x * 8 + w;
    float* expo = g_scratch + OFF_EXP;
    const uint4* w4 = (const uint4*)(g_wih_h + (size_t)j * H);
    uint4 wr[8];
    #pragma unroll
    for (int i = 0; i < 8; i++) wr[i] = w4[lane + i * 32];
    const float4* e4 = (const float4*)enc;
    #pragma unroll 1
    for (int e = 0; e < 9; e++) {
        float s = 0.0f;
        #pragma unroll
        for (int i = 0; i < 8; i++) {
            int idx = lane + i * 32;
            float4 ha = __ldg(&e4[e * 512 + idx * 2]);
            float4 hb = __ldg(&e4[e * 512 + idx * 2 + 1]);
            const __half2* hw = (const __half2*)&wr[i];
            float2 p0 = __half22float2(hw[0]);
            float2 p1 = __half22float2(hw[1]);
            float2 p2 = __half22float2(hw[2]);
            float2 p3 = __half22float2(hw[3]);
            s += p0.x * ha.x + p0.y * ha.y + p1.x * ha.z + p1.y * ha.w
               + p2.x * hb.x + p2.y * hb.y + p3.x * hb.z + p3.y * hb.w;
        }
        #pragma unroll
        for (int o = 16; o > 0; o >>= 1) s += __shfl_down_sync(0xffffffffu, s, o);
        if (lane == 0) expo[(size_t)e * G4 + j] = s;
    }
}

// --------------------------- dot helpers (R8 numerics) ---------------------
// fp16 weight row (SMEM) x fp32 h (SMEM stage). Same accumulation order as R8.
__device__ __forceinline__ float wdot_sm(const __half* __restrict__ ws,
                                         const float4* __restrict__ sh4,
                                         int lane)
{
    const uint4* w4 = (const uint4*)ws;
    uint4 wr[8];
    #pragma unroll
    for (int i = 0; i < 8; i++) wr[i] = w4[lane + i * 32];
    float s = 0.0f;
    #pragma unroll
    for (int i = 0; i < 8; i++) {
        int idx = lane + i * 32;
        float4 ha = sh4[idx * 2];
        float4 hb = sh4[idx * 2 + 1];
        const __half2* hw = (const __half2*)&wr[i];
        float2 p0 = __half22float2(hw[0]);
        float2 p1 = __half22float2(hw[1]);
        float2 p2 = __half22float2(hw[2]);
        float2 p3 = __half22float2(hw[3]);
        s += p0.x * ha.x + p0.y * ha.y + p1.x * ha.z + p1.y * ha.w
           + p2.x * hb.x + p2.y * hb.y + p3.x * hb.z + p3.y * hb.w;
    }
    #pragma unroll
    for (int o = 16; o > 0; o >>= 1) s += __shfl_down_sync(0xffffffffu, s, o);
    return s;
}

// fp16 weight row (GLOBAL, __ldcg) x fp32 h (SMEM stage)
__device__ __forceinline__ float wdot_g(const __half* __restrict__ wg,
                                        const float4* __restrict__ sh4,
                                        int lane)
{
    const uint4* w4 = (const uint4*)wg;
    uint4 wr[8];
    #pragma unroll
    for (int i = 0; i < 8; i++) wr[i] = __ldcg(w4 + lane + i * 32);
    float s = 0.0f;
    #pragma unroll
    for (int i = 0; i < 8; i++) {
        int idx = lane + i * 32;
        float4 ha = sh4[idx * 2];
        float4 hb = sh4[idx * 2 + 1];
        const __half2* hw = (const __half2*)&wr[i];
        float2 p0 = __half22float2(hw[0]);
        float2 p1 = __half22float2(hw[1]);
        float2 p2 = __half22float2(hw[2]);
        float2 p3 = __half22float2(hw[3]);
        s += p0.x * ha.x + p0.y * ha.y + p1.x * ha.z + p1.y * ha.w
           + p2.x * hb.x + p2.y * hb.y + p3.x * hb.z + p3.y * hb.w;
    }
    #pragma unroll
    for (int o = 16; o > 0; o >>= 1) s += __shfl_down_sync(0xffffffffu, s, o);
    return s;
}

// ------------------------------- megakernel --------------------------------
__global__ void __launch_bounds__(TPB, 1)
mega_kernel(const float* __restrict__ w_hh,
            const float* __restrict__ b_soft,
            const float* __restrict__ b_nl,
            const float* __restrict__ v_at,
            float* __restrict__ out)
{
    extern __shared__ __align__(16) __half smw[];   // [CPB*4][H]
    __shared__ float4 sh4[512];                     // fp32 h stage (8KB)
    __shared__ float sredA[56];
    __shared__ float sredS[8];
    __shared__ float slog[10];

    const int b = blockIdx.x, t = threadIdx.x;
    const int w = t >> 5, lane = t & 31;

    float* scr  = g_scratch;
    float* hbuf[2] = { scr + OFF_H0, scr + OFF_H1 };
    float* cvec = scr + OFF_C;
    float* hw2  = scr + OFF_HW2;
    float* aw1  = scr + OFF_AW1;
    float* axp  = scr + OFF_AXP;
    float* expo = scr + OFF_EXP;
    float* bsum = scr + OFF_BSUM;

    const int c0 = b * CPB;
    const int has_extra = (b < XCOLS);
    const int xcol = 1924 + b;
    const int ntask = 52 + (has_extra ? 4 : 0);

    // ---- load this block's w_hh slice into SMEM (fp32 -> fp16), once ----
    {
        const float4* w4 = (const float4*)w_hh;
        uint2* d4 = (uint2*)smw;
        for (int i4 = t; i4 < 52 * 512; i4 += TPB) {
            int lr = i4 >> 9, c4 = i4 & 511;
            int gr = (lr & 3) * H + c0 + (lr >> 2);
            float4 v = __ldcg(&w4[(size_t)gr * 512 + c4]);
            __half2 a = __floats2half2_rn(v.x, v.y);
            __half2 bb = __floats2half2_rn(v.z, v.w);
            d4[(size_t)lr * 512 + c4] = make_uint2(*(unsigned*)&a, *(unsigned*)&bb);
        }
        __syncthreads();
    }

    int hp = 0, tc = 0;

    // LSTM step: stage fp32 h, dots from SMEM (+leftover from L2), optional
    // fused projections, epilogue, flip, barrier.
    #define LSTM_PHASE(XPB, TCI, OFFS, PM, AW1SLOT, AXPSLOT) do {            \
        if (t < 512) sh4[t] = ((const float4*)hbuf[hp])[t];                  \
        __syncthreads();                                                     \
        for (int task = w; task < ntask; task += 32) {                       \
            float s;                                                         \
            if (task < 52)                                                   \
                s = wdot_sm(smw + (size_t)task * H, sh4, lane);              \
            else                                                             \
                s = wdot_g(g_whh_x + ((size_t)((task - 52) * XCOLS + b)) * H,\
                           sh4, lane);                                       \
            if (lane == 0) sredA[task] = s;                                  \
        }                                                                    \
        if (PM) {                                                            \
            int total = ((PM) == 1) ? H : (H + G4);                          \
            int r0 = (b * total) / NBLK, r1 = ((b + 1) * total) / NBLK;      \
            for (int r = r0 + w; r < r1; r += 32) {                          \
                float s;                                                     \
                if (r < H) s = wdot_g(g_wa1_h + (size_t)r * H, sh4, lane);   \
                else       s = wdot_g(g_wih_h + (size_t)(r - H) * H, sh4,    \
                                      lane);                                 \
                if (lane == 0) {                                             \
                    if (r < H) (AW1SLOT)[r] = s;                             \
                    else       (AXPSLOT)[r - H] = s;                         \
                }                                                            \
            }                                                                \
        }                                                                    \
        __syncthreads();                                                     \
        if (t < CPB || (t == CPB && has_extra)) {                            \
            int j    = (t < CPB) ? (c0 + t) : xcol;                          \
            int base = (t < CPB) ? (t * 4) : 52;                             \
            int slot = ((TCI) < 0) ? 0 : (g_sel[(TCI)] + (OFFS));            \
            const float* xp = (XPB) + (size_t)slot * G4;                     \
            float gi = sredA[base + 0] + xp[j]       + bsum[j];              \
            float gf = sredA[base + 1] + xp[j + H]   + bsum[j + H];          \
            float gg = sredA[base + 2] + xp[j + 2*H] + bsum[j + 2*H];        \
            float go = sredA[base + 3] + xp[j + 3*H] + bsum[j + 3*H];        \
            float si = 1.0f / (1.0f + expf(-gi));                            \
            float sf = 1.0f / (1.0f + expf(-gf));                            \
            float so = 1.0f / (1.0f + expf(-go));                            \
            float cn = sf * cvec[j] + si * tanhf(gg);                        \
            cvec[j] = cn;                                                    \
            hbuf[hp ^ 1][j] = so * tanhf(cn);                                \
        }                                                                    \
        hp ^= 1;                                                             \
        gbar();                                                              \
    } while (0)

    // attn matvec: hw2 = w_a2 @ h, distributed; h staged fp32
    #define ATTN_MV_PHASE() do {                                             \
        if (t < 512) sh4[t] = ((const float4*)hbuf[hp])[t];                  \
        __syncthreads();                                                     \
        int r0 = (b * H) / NBLK, r1 = ((b + 1) * H) / NBLK;                  \
        for (int r = r0 + w; r < r1; r += 32) {                              \
            float s = wdot_g(g_wa2_h + (size_t)r * H, sh4, lane);            \
            if (lane == 0) hw2[r] = s;                                       \
        }                                                                    \
        gbar();                                                              \
    } while (0)

    #define IDX_SAMPLE_PHASE(N, OUTP) do {                                   \
        if (b == 0) {                                                        \
            for (int a = 0; a < (N); a++) {                                  \
                float ss = 0.0f;                                             \
                if (t < 256)                                                 \
                    for (int k = t; k < H; k += 256)                         \
                        ss += tanhf(aw1[(size_t)a * H + k] + hw2[k])         \
                              * v_at[k];                                     \
                for (int o = 16; o > 0; o >>= 1)                             \
                    ss += __shfl_down_sync(0xffffffffu, ss, o);              \
                if (w < 8 && lane == 0) sredS[w] = ss;                       \
                __syncthreads();                                             \
                if (t == 0) {                                                \
                    float tot = 0.0f;                                        \
                    for (int wp = 0; wp < 8; wp++) tot += sredS[wp];         \
                    slog[a] = tot;                                           \
                }                                                            \
                __syncthreads();                                             \
            }                                                                \
            if (t == 0) {                                                    \
                float l[10];                                                 \
                for (int a = 0; a < (N); a++)                                \
                    l[a] = 2.5f * tanhf(slog[a] / 5.0f);                     \
                do_sample(l, (N), &g_sel[tc], (OUTP));                       \
            }                                                                \
        }                                                                    \
        gbar();                                                              \
    } while (0)

    #define OP_SAMPLE_PHASE(UB, OUTP) do {                                   \
        if (b == 0) {                                                        \
            const float* hcur = hbuf[hp];                                    \
            for (int rr = 0; rr < 8; rr++) {                                 \
                float ss = 0.0f;                                             \
                if (t < 256)                                                 \
                    for (int k = t; k < H; k += 256)                         \
                        ss += hcur[k]                                        \
                            * __half2float(g_wsoft_h[(size_t)rr * H + k]);   \
                for (int o = 16; o > 0; o >>= 1)                             \
                    ss += __shfl_down_sync(0xffffffffu, ss, o);              \
                if (w < 8 && lane == 0) sredS[w] = ss;                       \
                __syncthreads();                                             \
                if (t == 0) {                                                \
                    float tot = 0.0f;                                        \
                    for (int wp = 0; wp < 8; wp++) tot += sredS[wp];         \
                    slog[rr] = tot;                                          \
                }                                                            \
                __syncthreads();                                             \
            }                                                                \
            if (t == 0) {                                                    \
                float l[8];                                                  \
                for (int rr = 0; rr < 8; rr++) {                             \
                    float v = tanhf((slog[rr] + b_soft[rr]) / 5.0f);         \
                    if (UB) v += b_nl[rr];                                   \
                    l[rr] = v;                                               \
                }                                                            \
                do_sample(l, 8, &g_sel[tc], (OUTP));                         \
            }                                                                \
        }                                                                    \
        gbar();                                                              \
    } while (0)

    // ------------------------------ schedule -------------------------------
    for (int s = 0; s < 2; s++) {
        int ub = (s == 0) ? 1 : 0;
        LSTM_PHASE(expo, -1, 0, 0, aw1, axp);                       // warmup w0
        LSTM_PHASE(expo, -1, 0, 1, aw1 + 0 * H, axp);               // warmup w1

        for (int l = 0; l < 8; l++) {
            int n = l + 2;
            int base = s * 32 + l * 4;
            // idx0 + fused proj of prev h into slot l+1 (slot 9 dropped)
            if (l == 0) { LSTM_PHASE(expo, -1, 0, 1, aw1 + (size_t)1 * H, axp); }
            else        { LSTM_PHASE(expo, -1, 0, 2, aw1 + (size_t)(l+1) * H,
                                     axp + (size_t)(l+1) * G4); }
            ATTN_MV_PHASE();
            IDX_SAMPLE_PHASE(n, out + base + 0);
            int t0 = tc++;
            LSTM_PHASE(axp, t0, 0, 0, aw1, axp);                    // idx1
            ATTN_MV_PHASE();
            IDX_SAMPLE_PHASE(n, out + base + 2);
            int t1 = tc++;
            LSTM_PHASE(axp, t1, 0, 0, aw1, axp);                    // op0
            OP_SAMPLE_PHASE(ub, out + base + 1);
            int t2 = tc++;
            LSTM_PHASE(expo, t2, 1, 0, aw1, axp);                   // op1
            OP_SAMPLE_PHASE(ub, out + base + 3);
            int t3 = tc++;
            LSTM_PHASE(expo, t3, 1, 0, aw1, axp);                   // anchor
        }
    }
    if (b == 0 && t == 0) {
        out[64] = g_acc[0];
        out[65] = g_acc[1];
    }
    #undef LSTM_PHASE
    #undef ATTN_MV_PHASE
    #undef IDX_SAMPLE_PHASE
    #undef OP_SAMPLE_PHASE
}

// ------------------------------- launcher ----------------------------------
extern "C" void kernel_launch(void* const* d_in, const int* in_sizes, int n_in,
                              void* d_out, int out_size)
{
    const float* enc    = (const float*)d_in[0];
    const float* w_ih   = (const float*)d_in[1];
    const float* b_ih   = (const float*)d_in[2];
    const float* w_hh   = (const float*)d_in[3];
    const float* b_hh   = (const float*)d_in[4];
    const float* w_soft = (const float*)d_in[5];
    const float* b_soft = (const float*)d_in[6];
    const float* b_nl   = (const float*)d_in[7];
    const float* w_a1   = (const float*)d_in[8];
    const float* w_a2   = (const float*)d_in[9];
    const float* v_at   = (const float*)d_in[10];
    float* out = (float*)d_out;

    cudaFuncSetAttribute(mega_kernel,
                         cudaFuncAttributeMaxDynamicSharedMemorySize,
                         SMEM_BYTES);

    init_kernel<<<64, 256>>>(b_ih, b_hh);
    convert_kernel<<<2048, 256>>>(w_hh, w_ih, w_a1, w_a2, w_soft);
    encproj_kernel<<<1024, 256>>>(enc);
    mega_kernel<<<NBLK, TPB, SMEM_BYTES>>>(w_hh, b_soft, b_nl, v_at, out);
}